// round 15
// baseline (speedup 1.0000x reference)
#include <cuda_runtime.h>
#include <cuda_bf16.h>
#include <cstdint>

#define NN 16384
#define KN 25
#define DD 256
#define LL 64
#define NPC 2                   // nodes per CTA
#define ROWS (NPC * KN)         // 50
#define MM 64                   // padded MMA M
#define NCTA (NN / NPC)         // 8192 (exact)
#define AST 68                  // A smem row stride in u32 (conflict-free frags)

// device scratch (no allocation allowed)
__device__ float g_expected[NN * DD];
__device__ uint2 g_Bfrag[DD * 8 * 4];    // W_link tf32 frags (kernel A)
__device__ uint4 g_Wfrag[2 * 32 * 4 * DD]; // W_self/W_neigh frags {hi0,hi1,lo0,lo1}
__device__ float g_ts[NN];

typedef unsigned int uint;
typedef unsigned long long ull;

// ---------------- kernel A smem layout (bytes) -----------------------------
#define NEIGH_OFF   0           // 50*256*4  = 51200
#define A_OFF       51200       // 64*68*4   = 17408 (tf32)
#define DBUF_OFF    68608       // 32*260*4  = 33280
#define EXP_OFF     101888      // 2*256*4   = 2048
#define TLINK_OFF   103936
#define TNEIGH_OFF  104192
#define WK_OFF      104448
#define GNW_OFF     104704
#define GLW_OFF     105728
#define SMEM_TOTAL  105984      // ~103.5 KB -> 2 CTAs/SM

// ---------------- fused gemm smem layout -----------------------------------
#define G_AHI_OFF   0           // 64*68*4 = 17408
#define G_ALO_OFF   17408       // 17408
#define G_WF_OFF    34816       // 8kk*4tig*64n*16B = 32768
#define G_SMEM      67584       // ~66 KB -> 3 CTAs/SM

__device__ __forceinline__ uint tf32r(float x) {
    uint r; asm("cvt.rna.tf32.f32 %0, %1;" : "=r"(r) : "f"(x)); return r;
}
__device__ __forceinline__ float sigm_fast(float x) {
    float th;
    asm("tanh.approx.f32 %0, %1;" : "=f"(th) : "f"(0.5f * x));
    return fmaf(0.5f, th, 0.5f);
}
__device__ __forceinline__ void mma_tf32(float* c, const uint* a, uint b0, uint b1) {
    asm volatile(
        "mma.sync.aligned.m16n8k8.row.col.f32.tf32.tf32.f32 "
        "{%0,%1,%2,%3}, {%4,%5,%6,%7}, {%8,%9}, {%0,%1,%2,%3};"
        : "+f"(c[0]), "+f"(c[1]), "+f"(c[2]), "+f"(c[3])
        : "r"(a[0]), "r"(a[1]), "r"(a[2]), "r"(a[3]), "r"(b0), "r"(b1));
}
__device__ __forceinline__ uint smem_u32(const void* p) {
    uint a; asm("{ .reg .u64 t; cvta.to.shared.u64 t, %1; cvt.u32.u64 %0, t; }"
                : "=r"(a) : "l"(p));
    return a;
}
__device__ __forceinline__ void cp_async16(uint smem_addr, const void* gptr) {
    asm volatile("cp.async.cg.shared.global [%0], [%1], 16;"
                 :: "r"(smem_addr), "l"(gptr) : "memory");
}
#define CP_COMMIT() asm volatile("cp.async.commit_group;" ::: "memory")
#define CP_WAIT0()  asm volatile("cp.async.wait_group 0;" ::: "memory")

// ---------------------------------------------------------------------------
// Precursor 1: W_link -> tf32 B-fragments (kernel A)   [proven]
// ---------------------------------------------------------------------------
__global__ void conv_w_kernel(const float* __restrict__ W_link) {
    int idx = blockIdx.x * 256 + threadIdx.x;   // 0..8191
    int n   = idx >> 5;
    int kk  = (idx >> 2) & 7;
    int tig = idx & 3;
    int l0  = 8 * kk + tig;
    uint2 v;
    v.x = tf32r(W_link[l0 * DD + n]);
    v.y = tf32r(W_link[(l0 + 4) * DD + n]);
    g_Bfrag[idx] = v;
}

// Precursor 1b: W_self/W_neigh -> hi/lo tf32 fragments for the fused gemm.
//   g_Wfrag[h*32768 + kkg*1024 + tig*256 + n] = {hi0, hi1, lo0, lo1}
//   where hi_j/lo_j split W[(8kkg+tig+4j)*256 + n].
__global__ void conv_w2_kernel(const float* __restrict__ Wself,
                               const float* __restrict__ Wneigh) {
    int idx = blockIdx.x * 256 + threadIdx.x;   // 0..65535
    int n   = idx & 255;
    int tig = (idx >> 8) & 3;
    int kkg = (idx >> 10) & 31;
    int h   = idx >> 15;
    const float* W = h ? Wneigh : Wself;
    float w0 = W[(8 * kkg + tig) * DD + n];
    float w1 = W[(8 * kkg + tig + 4) * DD + n];
    uint h0 = tf32r(w0), h1 = tf32r(w1);
    uint l0 = tf32r(w0 - __uint_as_float(h0));
    uint l1 = tf32r(w1 - __uint_as_float(h1));
    g_Wfrag[idx] = make_uint4(h0, h1, l0, l1);
}

// Precursor 2: g_ts[n] = self_vecs[n] . g_self_w   [proven]
__global__ void ts_kernel(const float* __restrict__ self_vecs,
                          const float* __restrict__ g_self_w) {
    int warp = (blockIdx.x * 256 + threadIdx.x) >> 5;
    int lane = threadIdx.x & 31;
    for (int n = warp; n < NN; n += 512) {
        float s = 0.f;
#pragma unroll
        for (int q = 0; q < 8; q++) {
            int d = lane + 32 * q;
            s = fmaf(self_vecs[n * DD + d], g_self_w[d], s);
        }
#pragma unroll
        for (int o = 16; o > 0; o >>= 1) s += __shfl_xor_sync(0xffffffffu, s, o);
        if (lane == 0) g_ts[n] = s;
    }
}

// ---------------------------------------------------------------------------
// Kernel A: byte-identical to the passing R12 kernel (424 us total).
// ---------------------------------------------------------------------------
__global__ __launch_bounds__(256, 2) void mma_agg_kernel(
    const float* __restrict__ neigh_vecs,
    const float* __restrict__ link_vecs,
    const float* __restrict__ select_probs,
    const float* __restrict__ g_neigh_w,
    const float* __restrict__ g_link_w)
{
    extern __shared__ char sm[];
    const uint sb  = smem_u32(sm);
    const int t    = threadIdx.x;
    const int wid  = t >> 5;
    const int lane = t & 31;
    const int g8   = lane >> 2;
    const int tig  = lane & 3;
    const int b    = blockIdx.x;

    float*  neigh_s  = (float*)(sm + NEIGH_OFF);
    uint*   Asm      = (uint*)(sm + A_OFF);
    float*  dbuf     = (float*)(sm + DBUF_OFF);
    float*  exp_s    = (float*)(sm + EXP_OFF);
    float*  tlink_s  = (float*)(sm + TLINK_OFF);
    float*  tneigh_s = (float*)(sm + TNEIGH_OFF);
    float*  wk_s     = (float*)(sm + WK_OFF);
    float*  gnw_s    = (float*)(sm + GNW_OFF);
    float*  glw_s    = (float*)(sm + GLW_OFF);

    // step 0: issue neigh stream FIRST
    {
        const float4* src = (const float4*)(neigh_vecs + (long)b * ROWS * DD);
        for (int idx = t; idx < (ROWS * DD) / 4; idx += 256)
            cp_async16(sb + NEIGH_OFF + idx * 16, src + idx);
        CP_COMMIT();
    }

    // step 0b: small vectors + zero init
    gnw_s[t] = g_neigh_w[t];
    if (t < LL) glw_s[t] = g_link_w[t];
    if (t < MM) wk_s[t] = 0.f;
    exp_s[t] = 0.f; exp_s[256 + t] = 0.f;
    __syncthreads();   // glw_s visible before step 1 reads it

    // step 1: stage A as tf32 [64, AST] + tlink partial dots
    {
        int r = t >> 2, q = t & 3;
        bool valid = r < ROWS;
        const float4* src = (const float4*)(link_vecs + ((long)b * ROWS + r) * LL + 16 * q);
        const float4 z4 = make_float4(0.f, 0.f, 0.f, 0.f);
        float dl = 0.f;
#pragma unroll
        for (int u = 0; u < 4; u++) {
            float4 x = valid ? src[u] : z4;
            uint4 c4 = make_uint4(tf32r(x.x), tf32r(x.y), tf32r(x.z), tf32r(x.w));
            *(uint4*)&Asm[r * AST + 16 * q + 4 * u] = c4;
            int lb = 16 * q + 4 * u;
            dl = fmaf(x.x, glw_s[lb],     dl);
            dl = fmaf(x.y, glw_s[lb + 1], dl);
            dl = fmaf(x.z, glw_s[lb + 2], dl);
            dl = fmaf(x.w, glw_s[lb + 3], dl);
        }
        dl += __shfl_xor_sync(0xffffffffu, dl, 1);
        dl += __shfl_xor_sync(0xffffffffu, dl, 2);
        if (q == 0 && valid) tlink_s[r] = dl;
    }
    __syncthreads();

    // step 2: MMA while neigh stream is in flight
    float acc[4][4][4];
#pragma unroll
    for (int mi = 0; mi < 4; mi++)
#pragma unroll
        for (int ni = 0; ni < 4; ni++)
#pragma unroll
            for (int j = 0; j < 4; j++) acc[mi][ni][j] = 0.f;

#pragma unroll
    for (int kk = 0; kk < 8; kk++) {
        uint af[4][4];
#pragma unroll
        for (int mi = 0; mi < 4; mi++) {
            int e = (16 * mi + g8) * AST + 8 * kk + tig;
            af[mi][0] = Asm[e];
            af[mi][1] = Asm[e + 8 * AST];
            af[mi][2] = Asm[e + 4];
            af[mi][3] = Asm[e + 8 * AST + 4];
        }
#pragma unroll
        for (int ni = 0; ni < 4; ni++) {
            int n = 32 * wid + 8 * ni + g8;
            uint2 bb = g_Bfrag[(n * 8 + kk) * 4 + tig];
#pragma unroll
            for (int mi = 0; mi < 4; mi++)
                mma_tf32(acc[mi][ni], af[mi], bb.x, bb.y);
        }
    }

    // step 3: neigh must be resident now
    CP_WAIT0();
    __syncthreads();

    // step 4: gate — trans_neigh warp-task dots, then wk
    for (int task = wid; task < ROWS; task += 8) {
        float s = 0.f;
#pragma unroll
        for (int q = 0; q < 8; q++) {
            int d = lane + 32 * q;
            s = fmaf(neigh_s[task * DD + d], gnw_s[d], s);
        }
#pragma unroll
        for (int o = 16; o > 0; o >>= 1) s += __shfl_xor_sync(0xffffffffu, s, o);
        if (lane == 0) tneigh_s[task] = s;
    }
    __syncthreads();
    if (t < ROWS) {
        int node = t / KN, k = t - node * KN;
        int n = b * NPC + node;
        float r  = g_ts[n] + tneigh_s[t] + tlink_s[t];
        float gt = 1.f / (1.f + __expf(-r));
        wk_s[t]  = gt / (select_probs[n * KN + k] * (float)KN);
    }
    __syncthreads();

    // step 5: epilogue in two 32-row chunks
#pragma unroll
    for (int c = 0; c < 2; c++) {
#pragma unroll
        for (int mi = 0; mi < 4; mi++) {
            if ((mi >> 1) == c) {
                int mm2  = mi & 1;
                int row0 = 16 * mi + g8;
                float w0 = wk_s[row0], w1 = wk_s[row0 + 8];
#pragma unroll
                for (int ni = 0; ni < 4; ni++) {
                    int col = 32 * wid + 8 * ni + 2 * tig;
                    float2 v0, v1;
                    v0.x = sigm_fast(acc[mi][ni][0]) * w0;
                    v0.y = sigm_fast(acc[mi][ni][1]) * w0;
                    v1.x = sigm_fast(acc[mi][ni][2]) * w1;
                    v1.y = sigm_fast(acc[mi][ni][3]) * w1;
                    *(float2*)&dbuf[(16 * mm2 + g8) * 260 + col]     = v0;
                    *(float2*)&dbuf[(16 * mm2 + g8 + 8) * 260 + col] = v1;
                }
            }
        }
        __syncthreads();
        int r0 = 32 * c;
#pragma unroll
        for (int i = 0; i < NPC; i++) {
            int lo = KN * i > r0 ? KN * i : r0;
            int hi = KN * i + KN < r0 + 32 ? KN * i + KN : r0 + 32;
            float a = 0.f;
            for (int j = lo; j < hi; j++)
                a = fmaf(dbuf[(j - r0) * 260 + t], neigh_s[j * DD + t], a);
            exp_s[i * DD + t] += a;
        }
        __syncthreads();
    }

    // step 6: write expected
#pragma unroll
    for (int i = 0; i < NPC; i++)
        g_expected[((long)b * NPC + i) * DD + t] = exp_s[i * DD + t];
}

// ---------------------------------------------------------------------------
// Fused output GEMM (tf32 3-term split):
//   blockIdx.y>>2 == 0:  out[:,   0:256] = relu(self_vecs @ W_self)
//   blockIdx.y>>2 == 1:  out[:, 256:512] = relu(g_expected @ W_neigh)
// 64x64 tile per CTA; W chunk cp.async-staged; A chunk staged+split in smem.
// ---------------------------------------------------------------------------
__global__ __launch_bounds__(256) void gemm_fused_kernel(
    const float* __restrict__ self_vecs, float* __restrict__ out)
{
    extern __shared__ char sg[];
    const uint sb = smem_u32(sg);
    uint*  Ahi = (uint*)(sg + G_AHI_OFF);
    uint*  Alo = (uint*)(sg + G_ALO_OFF);
    uint4* Wf  = (uint4*)(sg + G_WF_OFF);     // [kk*4+tig][64] local n

    const int t    = threadIdx.x;
    const int wid  = t >> 5;
    const int lane = t & 31;
    const int g8   = lane >> 2;
    const int tig  = lane & 3;
    const int wr   = wid & 3;       // m-tile (16 rows)
    const int wc   = wid >> 2;      // 32-col group
    const int r0   = blockIdx.x * 64;
    const int h    = blockIdx.y >> 2;
    const int ct   = blockIdx.y & 3;
    const float* __restrict__ A = h ? (const float*)g_expected : self_vecs;

    float acc[4][4];
#pragma unroll
    for (int ni = 0; ni < 4; ni++)
#pragma unroll
        for (int j = 0; j < 4; j++) acc[ni][j] = 0.f;

    for (int kc = 0; kc < 4; kc++) {
        // W chunk via cp.async: 2048 uint4 (32 KB), thread does 8
#pragma unroll
        for (int u = 0; u < 8; u++) {
            int e    = t + u * 256;            // dest Wf[e]
            int kk   = e >> 8;
            int tg2  = (e >> 6) & 3;
            int nl   = e & 63;
            const uint4* s = g_Wfrag + (((h * 32 + 8 * kc + kk) * 4 + tg2) * 256
                                        + 64 * ct + nl);
            cp_async16(sb + G_WF_OFF + e * 16, s);
        }
        CP_COMMIT();

        // A chunk staging + hi/lo split (overlaps the W stream)
        {
            int row = t >> 2, q = t & 3;
            const float4* src = (const float4*)(A + (size_t)(r0 + row) * DD
                                                + kc * 64 + q * 16);
#pragma unroll
            for (int u = 0; u < 4; u++) {
                float4 x = src[u];
                uint4 hi = make_uint4(tf32r(x.x), tf32r(x.y), tf32r(x.z), tf32r(x.w));
                uint4 lo = make_uint4(tf32r(x.x - __uint_as_float(hi.x)),
                                      tf32r(x.y - __uint_as_float(hi.y)),
                                      tf32r(x.z - __uint_as_float(hi.z)),
                                      tf32r(x.w - __uint_as_float(hi.w)));
                *(uint4*)&Ahi[row * AST + q * 16 + 4 * u] = hi;
                *(uint4*)&Alo[row * AST + q * 16 + 4 * u] = lo;
            }
        }
        CP_WAIT0();
        __syncthreads();

        // mma: 8 kk x 4 ni x 3 terms
#pragma unroll
        for (int kk = 0; kk < 8; kk++) {
            int e = (16 * wr + g8) * AST + 8 * kk + tig;
            uint ah[4], al[4];
            ah[0] = Ahi[e];             ah[1] = Ahi[e + 8 * AST];
            ah[2] = Ahi[e + 4];         ah[3] = Ahi[e + 8 * AST + 4];
            al[0] = Alo[e];             al[1] = Alo[e + 8 * AST];
            al[2] = Alo[e + 4];         al[3] = Alo[e + 8 * AST + 4];
#pragma unroll
            for (int ni = 0; ni < 4; ni++) {
                uint4 w = Wf[(kk * 4 + tig) * 64 + 32 * wc + 8 * ni + g8];
                mma_tf32(acc[ni], ah, w.x, w.y);   // hi * hi
                mma_tf32(acc[ni], ah, w.z, w.w);   // hi * lo
                mma_tf32(acc[ni], al, w.x, w.y);   // lo * hi
            }
        }
        __syncthreads();
    }

    // epilogue: relu + store
    const int colb = h * 256 + ct * 64 + wc * 32;
    const int row0 = r0 + 16 * wr + g8;
#pragma unroll
    for (int ni = 0; ni < 4; ni++) {
        int col = colb + 8 * ni + 2 * tig;
        float2 v0, v1;
        v0.x = fmaxf(acc[ni][0], 0.f);
        v0.y = fmaxf(acc[ni][1], 0.f);
        v1.x = fmaxf(acc[ni][2], 0.f);
        v1.y = fmaxf(acc[ni][3], 0.f);
        *(float2*)&out[(size_t)row0 * 512 + col]       = v0;
        *(float2*)&out[(size_t)(row0 + 8) * 512 + col] = v1;
    }
}

extern "C" void kernel_launch(void* const* d_in, const int* in_sizes, int n_in,
                              void* d_out, int out_size)
{
    const float* self_vecs    = (const float*)d_in[0];
    const float* neigh_vecs   = (const float*)d_in[1];
    const float* link_vecs    = (const float*)d_in[2];
    const float* select_probs = (const float*)d_in[3];
    const float* g_self_w     = (const float*)d_in[4];
    const float* g_neigh_w    = (const float*)d_in[5];
    const float* g_link_w     = (const float*)d_in[6];
    const float* W_link       = (const float*)d_in[7];
    const float* W_self       = (const float*)d_in[8];
    const float* W_neigh      = (const float*)d_in[9];
    float* out = (float*)d_out;

    static int attr_set = 0;
    if (!attr_set) {
        cudaFuncSetAttribute(mma_agg_kernel,
                             cudaFuncAttributeMaxDynamicSharedMemorySize, SMEM_TOTAL);
        cudaFuncSetAttribute(gemm_fused_kernel,
                             cudaFuncAttributeMaxDynamicSharedMemorySize, G_SMEM);
        attr_set = 1;
    }

    conv_w_kernel<<<32, 256>>>(W_link);
    conv_w2_kernel<<<256, 256>>>(W_self, W_neigh);
    ts_kernel<<<64, 256>>>(self_vecs, g_self_w);

    mma_agg_kernel<<<NCTA, 256, SMEM_TOTAL>>>(neigh_vecs, link_vecs, select_probs,
                                              g_neigh_w, g_link_w);

    gemm_fused_kernel<<<dim3(NN / 64, 8), 256, G_SMEM>>>(self_vecs, out);
}

// round 16
// speedup vs baseline: 1.0117x; 1.0117x over previous
#include <cuda_runtime.h>
#include <cuda_bf16.h>
#include <cstdint>

#define NN 16384
#define KN 25
#define DD 256
#define LL 64
#define ROWS KN                 // 25 rows (1 node per CTA)
#define MM 32                   // padded MMA M
#define NCTA NN                 // 16384 CTAs
#define AST 68                  // A smem row stride in u32 (conflict-free frags)

// device scratch (no allocation allowed)
__device__ float g_expected[NN * DD];
__device__ uint2 g_Bfrag[DD * 8 * 4];   // [n][kk][tig] tf32 W_link frags
__device__ float g_ts[NN];

typedef unsigned int uint;
typedef unsigned long long ull;

// ---------------- kernel A smem layout (bytes) -----------------------------
#define NEIGH_OFF   0           // 25*256*4 = 25600
#define A_OFF       25600       // 32*68*4  = 8704
#define DBUF_OFF    34304       // 32*260*4 = 33280
#define TLINK_OFF   67584       // 32*4
#define TNEIGH_OFF  67712       // 32*4
#define WK_OFF      67840       // 32*4
#define GNW_OFF     67968       // 256*4
#define GLW_OFF     68992       // 64*4
#define SMEM_TOTAL  69248       // 67.6 KB -> 3 CTAs/SM (207.7 KB of 227)

__device__ __forceinline__ uint tf32r(float x) {
    uint r; asm("cvt.rna.tf32.f32 %0, %1;" : "=r"(r) : "f"(x)); return r;
}
__device__ __forceinline__ float sigm_fast(float x) {
    float th;
    asm("tanh.approx.f32 %0, %1;" : "=f"(th) : "f"(0.5f * x));
    return fmaf(0.5f, th, 0.5f);
}
__device__ __forceinline__ void mma_tf32(float* c, const uint* a, uint b0, uint b1) {
    asm volatile(
        "mma.sync.aligned.m16n8k8.row.col.f32.tf32.tf32.f32 "
        "{%0,%1,%2,%3}, {%4,%5,%6,%7}, {%8,%9}, {%0,%1,%2,%3};"
        : "+f"(c[0]), "+f"(c[1]), "+f"(c[2]), "+f"(c[3])
        : "r"(a[0]), "r"(a[1]), "r"(a[2]), "r"(a[3]), "r"(b0), "r"(b1));
}
__device__ __forceinline__ uint smem_u32(const void* p) {
    uint a; asm("{ .reg .u64 t; cvta.to.shared.u64 t, %1; cvt.u32.u64 %0, t; }"
                : "=r"(a) : "l"(p));
    return a;
}
__device__ __forceinline__ void cp_async16(uint smem_addr, const void* gptr) {
    asm volatile("cp.async.cg.shared.global [%0], [%1], 16;"
                 :: "r"(smem_addr), "l"(gptr) : "memory");
}
#define CP_COMMIT() asm volatile("cp.async.commit_group;" ::: "memory")
#define CP_WAIT0()  asm volatile("cp.async.wait_group 0;" ::: "memory")

// ---------------------------------------------------------------------------
// Precursor 1: W_link -> tf32 B-fragments   [proven]
// ---------------------------------------------------------------------------
__global__ void conv_w_kernel(const float* __restrict__ W_link) {
    int idx = blockIdx.x * 256 + threadIdx.x;   // 0..8191
    int n   = idx >> 5;
    int kk  = (idx >> 2) & 7;
    int tig = idx & 3;
    int l0  = 8 * kk + tig;
    uint2 v;
    v.x = tf32r(W_link[l0 * DD + n]);
    v.y = tf32r(W_link[(l0 + 4) * DD + n]);
    g_Bfrag[idx] = v;
}

// Precursor 2: g_ts[n] = self_vecs[n] . g_self_w   [proven]
__global__ void ts_kernel(const float* __restrict__ self_vecs,
                          const float* __restrict__ g_self_w) {
    int warp = (blockIdx.x * 256 + threadIdx.x) >> 5;
    int lane = threadIdx.x & 31;
    for (int n = warp; n < NN; n += 512) {
        float s = 0.f;
#pragma unroll
        for (int q = 0; q < 8; q++) {
            int d = lane + 32 * q;
            s = fmaf(self_vecs[n * DD + d], g_self_w[d], s);
        }
#pragma unroll
        for (int o = 16; o > 0; o >>= 1) s += __shfl_xor_sync(0xffffffffu, s, o);
        if (lane == 0) g_ts[n] = s;
    }
}

// ---------------------------------------------------------------------------
// Kernel A (NPC=1): one node per CTA, 25 rows padded to M=32.
//   Proven R12 phase structure (cp.async neigh stream overlapped with the
//   tf32 MMA), indices halved: acc[2][4][4]=32 regs, smem 67.6 KB
//   -> 3 CTAs/SM (24 warps) for +50% latency-hiding concurrency.
// ---------------------------------------------------------------------------
__global__ __launch_bounds__(256, 3) void mma_agg_kernel(
    const float* __restrict__ neigh_vecs,
    const float* __restrict__ link_vecs,
    const float* __restrict__ select_probs,
    const float* __restrict__ g_neigh_w,
    const float* __restrict__ g_link_w)
{
    extern __shared__ char sm[];
    const uint sb  = smem_u32(sm);
    const int t    = threadIdx.x;
    const int wid  = t >> 5;
    const int lane = t & 31;
    const int g8   = lane >> 2;
    const int tig  = lane & 3;
    const int b    = blockIdx.x;

    float*  neigh_s  = (float*)(sm + NEIGH_OFF);
    uint*   Asm      = (uint*)(sm + A_OFF);
    float*  dbuf     = (float*)(sm + DBUF_OFF);
    float*  tlink_s  = (float*)(sm + TLINK_OFF);
    float*  tneigh_s = (float*)(sm + TNEIGH_OFF);
    float*  wk_s     = (float*)(sm + WK_OFF);
    float*  gnw_s    = (float*)(sm + GNW_OFF);
    float*  glw_s    = (float*)(sm + GLW_OFF);

    // step 0: issue neigh stream FIRST (fire-and-forget)
    {
        const float4* src = (const float4*)(neigh_vecs + (long)b * ROWS * DD);
        for (int idx = t; idx < (ROWS * DD) / 4; idx += 256)
            cp_async16(sb + NEIGH_OFF + idx * 16, src + idx);
        CP_COMMIT();
    }

    // step 0b: small vectors + zero wk padding rows
    gnw_s[t] = g_neigh_w[t];
    if (t < LL) glw_s[t] = g_link_w[t];
    if (t < MM) wk_s[t] = 0.f;
    __syncthreads();   // glw_s visible before step 1 reads it (R10 lesson)

    // step 1: stage A as tf32 [32, AST] + tlink partial dots
    // 8 threads per row (q = 8-elem chunk), rows 0..31, valid rows < 25
    {
        int r = t >> 3, q = t & 7;
        bool valid = r < ROWS;
        const float4* src = (const float4*)(link_vecs + ((long)b * ROWS + r) * LL + 8 * q);
        const float4 z4 = make_float4(0.f, 0.f, 0.f, 0.f);
        float dl = 0.f;
#pragma unroll
        for (int u = 0; u < 2; u++) {
            float4 x = valid ? src[u] : z4;
            uint4 c4 = make_uint4(tf32r(x.x), tf32r(x.y), tf32r(x.z), tf32r(x.w));
            *(uint4*)&Asm[r * AST + 8 * q + 4 * u] = c4;
            int lb = 8 * q + 4 * u;
            dl = fmaf(x.x, glw_s[lb],     dl);
            dl = fmaf(x.y, glw_s[lb + 1], dl);
            dl = fmaf(x.z, glw_s[lb + 2], dl);
            dl = fmaf(x.w, glw_s[lb + 3], dl);
        }
        dl += __shfl_xor_sync(0xffffffffu, dl, 1);
        dl += __shfl_xor_sync(0xffffffffu, dl, 2);
        dl += __shfl_xor_sync(0xffffffffu, dl, 4);
        if (q == 0 && valid) tlink_s[r] = dl;
    }
    __syncthreads();   // Asm visible to all warps

    // step 2: MMA while neigh stream is in flight
    // S[32,256] = A[32,64] @ B[64,256]; warp w owns cols [32w, 32w+32)
    float acc[2][4][4];
#pragma unroll
    for (int mi = 0; mi < 2; mi++)
#pragma unroll
        for (int ni = 0; ni < 4; ni++)
#pragma unroll
            for (int j = 0; j < 4; j++) acc[mi][ni][j] = 0.f;

#pragma unroll
    for (int kk = 0; kk < 8; kk++) {
        uint af[2][4];
#pragma unroll
        for (int mi = 0; mi < 2; mi++) {
            int e = (16 * mi + g8) * AST + 8 * kk + tig;
            af[mi][0] = Asm[e];
            af[mi][1] = Asm[e + 8 * AST];
            af[mi][2] = Asm[e + 4];
            af[mi][3] = Asm[e + 8 * AST + 4];
        }
#pragma unroll
        for (int ni = 0; ni < 4; ni++) {
            int n = 32 * wid + 8 * ni + g8;
            uint2 bb = g_Bfrag[(n * 8 + kk) * 4 + tig];
#pragma unroll
            for (int mi = 0; mi < 2; mi++)
                mma_tf32(acc[mi][ni], af[mi], bb.x, bb.y);
        }
    }

    // step 3: neigh must be resident now
    CP_WAIT0();
    __syncthreads();

    // step 4: gate — trans_neigh warp-task dots, then wk
    for (int task = wid; task < ROWS; task += 8) {
        float s = 0.f;
#pragma unroll
        for (int q = 0; q < 8; q++) {
            int d = lane + 32 * q;
            s = fmaf(neigh_s[task * DD + d], gnw_s[d], s);
        }
#pragma unroll
        for (int o = 16; o > 0; o >>= 1) s += __shfl_xor_sync(0xffffffffu, s, o);
        if (lane == 0) tneigh_s[task] = s;
    }
    __syncthreads();
    if (t < ROWS) {
        float r  = g_ts[b] + tneigh_s[t] + tlink_s[t];
        float gt = 1.f / (1.f + __expf(-r));
        wk_s[t]  = gt / (select_probs[b * KN + t] * (float)KN);
    }
    __syncthreads();

    // step 5a: sigmoid * wk -> dbuf[32][260] (single chunk, all rows)
#pragma unroll
    for (int mi = 0; mi < 2; mi++) {
        int row0 = 16 * mi + g8;
        float w0 = wk_s[row0], w1 = wk_s[row0 + 8];
#pragma unroll
        for (int ni = 0; ni < 4; ni++) {
            int col = 32 * wid + 8 * ni + 2 * tig;
            float2 v0, v1;
            v0.x = sigm_fast(acc[mi][ni][0]) * w0;
            v0.y = sigm_fast(acc[mi][ni][1]) * w0;
            v1.x = sigm_fast(acc[mi][ni][2]) * w1;
            v1.y = sigm_fast(acc[mi][ni][3]) * w1;
            *(float2*)&dbuf[row0 * 260 + col]       = v0;
            *(float2*)&dbuf[(row0 + 8) * 260 + col] = v1;
        }
    }
    __syncthreads();

    // step 5b: reduce over k, write expected directly (col = t)
    {
        float a = 0.f;
#pragma unroll
        for (int j = 0; j < ROWS; j++)
            a = fmaf(dbuf[j * 260 + t], neigh_s[j * DD + t], a);
        g_expected[b * DD + t] = a;
    }
}

// ---------------------------------------------------------------------------
// Kernel B: out[:, coff:coff+256] = relu(A @ W)  (proven scalar FFMA2 pair)
// ---------------------------------------------------------------------------
__device__ __forceinline__ ull pk2(float lo, float hi) {
    ull r; asm("mov.b64 %0, {%1, %2};" : "=l"(r) : "f"(lo), "f"(hi)); return r;
}
__device__ __forceinline__ float2 upk2(ull v) {
    float2 f; asm("mov.b64 {%0, %1}, %2;" : "=f"(f.x), "=f"(f.y) : "l"(v)); return f;
}
__device__ __forceinline__ ull ffma2(ull a, ull b, ull c) {
    ull d; asm("fma.rn.f32x2 %0, %1, %2, %3;" : "=l"(d) : "l"(a), "l"(b), "l"(c)); return d;
}

__global__ __launch_bounds__(256) void gemm_relu_kernel(
    const float* __restrict__ A_in,
    const float* __restrict__ W,
    float* __restrict__ out,
    int coff, int use_expected)
{
    const float* __restrict__ A = use_expected ? (const float*)g_expected : A_in;

    __shared__ float As[64][32];
    __shared__ alignas(16) float Ws[32][64];

    const int tid = threadIdx.x;
    const int tx  = tid & 15;
    const int ty  = tid >> 4;
    const int r0  = blockIdx.x * 64;
    const int c0  = blockIdx.y * 64;

    ull acc[4][2];
#pragma unroll
    for (int i = 0; i < 4; i++) { acc[i][0] = 0ull; acc[i][1] = 0ull; }

    for (int kb = 0; kb < DD; kb += 32) {
#pragma unroll
        for (int u = 0; u < 2; u++) {
            int idx = tid + u * 256;
            int m = idx >> 3, q = idx & 7;
            *(float4*)&As[m][q * 4] =
                *(const float4*)&A[(size_t)(r0 + m) * DD + kb + q * 4];
        }
#pragma unroll
        for (int u = 0; u < 2; u++) {
            int idx = tid + u * 256;
            int kk = idx >> 4, q = idx & 15;
            *(float4*)&Ws[kk][q * 4] =
                *(const float4*)&W[(size_t)(kb + kk) * DD + c0 + q * 4];
        }
        __syncthreads();
#pragma unroll
        for (int kk = 0; kk < 32; kk++) {
            ulonglong2 b2 = *(const ulonglong2*)&Ws[kk][tx * 4];
#pragma unroll
            for (int i = 0; i < 4; i++) {
                float a = As[ty * 4 + i][kk];
                ull aa = pk2(a, a);
                acc[i][0] = ffma2(aa, b2.x, acc[i][0]);
                acc[i][1] = ffma2(aa, b2.y, acc[i][1]);
            }
        }
        __syncthreads();
    }

#pragma unroll
    for (int i = 0; i < 4; i++) {
        float2 r01 = upk2(acc[i][0]);
        float2 r23 = upk2(acc[i][1]);
        float4 o;
        o.x = fmaxf(r01.x, 0.f);
        o.y = fmaxf(r01.y, 0.f);
        o.z = fmaxf(r23.x, 0.f);
        o.w = fmaxf(r23.y, 0.f);
        *(float4*)&out[(size_t)(r0 + ty * 4 + i) * 512 + coff + c0 + tx * 4] = o;
    }
}

extern "C" void kernel_launch(void* const* d_in, const int* in_sizes, int n_in,
                              void* d_out, int out_size)
{
    const float* self_vecs    = (const float*)d_in[0];
    const float* neigh_vecs   = (const float*)d_in[1];
    const float* link_vecs    = (const float*)d_in[2];
    const float* select_probs = (const float*)d_in[3];
    const float* g_self_w     = (const float*)d_in[4];
    const float* g_neigh_w    = (const float*)d_in[5];
    const float* g_link_w     = (const float*)d_in[6];
    const float* W_link       = (const float*)d_in[7];
    const float* W_self       = (const float*)d_in[8];
    const float* W_neigh      = (const float*)d_in[9];
    float* out = (float*)d_out;

    static int attr_set = 0;
    if (!attr_set) {
        cudaFuncSetAttribute(mma_agg_kernel,
                             cudaFuncAttributeMaxDynamicSharedMemorySize, SMEM_TOTAL);
        attr_set = 1;
    }

    conv_w_kernel<<<32, 256>>>(W_link);
    ts_kernel<<<64, 256>>>(self_vecs, g_self_w);

    mma_agg_kernel<<<NCTA, 256, SMEM_TOTAL>>>(neigh_vecs, link_vecs, select_probs,
                                              g_neigh_w, g_link_w);

    dim3 g(NN / 64, 256 / 64);
    gemm_relu_kernel<<<g, 256>>>(self_vecs, W_self, out, 0, 0);
    gemm_relu_kernel<<<g, 256>>>(nullptr, W_neigh, out, 256, 1);
}

// round 17
// speedup vs baseline: 1.3330x; 1.3176x over previous
#include <cuda_runtime.h>
#include <cuda_bf16.h>
#include <cstdint>

#define NN 16384
#define KN 25
#define DD 256
#define LL 64
#define ROWS KN                 // 25 rows (1 node per iteration)
#define MM 32                   // padded MMA M
#define PCTA 296                // persistent CTAs (2 per SM)
#define AST 68                  // A smem row stride in u32 (conflict-free frags)

// device scratch (no allocation allowed)
__device__ float g_expected[NN * DD];
__device__ uint2 g_Bfrag[DD * 8 * 4];   // [n][kk][tig] tf32 W_link frags
__device__ float g_ts[NN];

typedef unsigned int uint;
typedef unsigned long long ull;

// ---------------- kernel A smem layout (bytes) -----------------------------
// two streaming slots: [neigh 25600 | link 6400] each
#define SLOT_SZ     32000
#define NEIGH_SZ    25600
#define SLOT_OFF    0           // 2 slots = 64000
#define A_OFF       64000       // 32*68*4 = 8704
#define DBUF_OFF    72704       // 32*260*4 = 33280
#define TLINK_OFF   105984      // 32*4
#define TNEIGH_OFF  106112      // 32*4
#define WK_OFF      106240      // 32*4
#define GNW_OFF     106368      // 256*4
#define GLW_OFF     107392      // 64*4
#define SMEM_TOTAL  107648      // 105.1 KB -> 2 CTAs/SM

__device__ __forceinline__ uint tf32r(float x) {
    uint r; asm("cvt.rna.tf32.f32 %0, %1;" : "=r"(r) : "f"(x)); return r;
}
__device__ __forceinline__ float sigm_fast(float x) {
    float th;
    asm("tanh.approx.f32 %0, %1;" : "=f"(th) : "f"(0.5f * x));
    return fmaf(0.5f, th, 0.5f);
}
__device__ __forceinline__ void mma_tf32(float* c, const uint* a, uint b0, uint b1) {
    asm volatile(
        "mma.sync.aligned.m16n8k8.row.col.f32.tf32.tf32.f32 "
        "{%0,%1,%2,%3}, {%4,%5,%6,%7}, {%8,%9}, {%0,%1,%2,%3};"
        : "+f"(c[0]), "+f"(c[1]), "+f"(c[2]), "+f"(c[3])
        : "r"(a[0]), "r"(a[1]), "r"(a[2]), "r"(a[3]), "r"(b0), "r"(b1));
}
__device__ __forceinline__ uint smem_u32(const void* p) {
    uint a; asm("{ .reg .u64 t; cvta.to.shared.u64 t, %1; cvt.u32.u64 %0, t; }"
                : "=r"(a) : "l"(p));
    return a;
}
__device__ __forceinline__ void cp_async16(uint smem_addr, const void* gptr) {
    asm volatile("cp.async.cg.shared.global [%0], [%1], 16;"
                 :: "r"(smem_addr), "l"(gptr) : "memory");
}
#define CP_COMMIT() asm volatile("cp.async.commit_group;" ::: "memory")
#define CP_WAIT1()  asm volatile("cp.async.wait_group 1;" ::: "memory")

// ---------------------------------------------------------------------------
// Precursor 1: W_link -> tf32 B-fragments   [proven]
// ---------------------------------------------------------------------------
__global__ void conv_w_kernel(const float* __restrict__ W_link) {
    int idx = blockIdx.x * 256 + threadIdx.x;   // 0..8191
    int n   = idx >> 5;
    int kk  = (idx >> 2) & 7;
    int tig = idx & 3;
    int l0  = 8 * kk + tig;
    uint2 v;
    v.x = tf32r(W_link[l0 * DD + n]);
    v.y = tf32r(W_link[(l0 + 4) * DD + n]);
    g_Bfrag[idx] = v;
}

// Precursor 2: g_ts[n] = self_vecs[n] . g_self_w   [proven]
__global__ void ts_kernel(const float* __restrict__ self_vecs,
                          const float* __restrict__ g_self_w) {
    int warp = (blockIdx.x * 256 + threadIdx.x) >> 5;
    int lane = threadIdx.x & 31;
    for (int n = warp; n < NN; n += 512) {
        float s = 0.f;
#pragma unroll
        for (int q = 0; q < 8; q++) {
            int d = lane + 32 * q;
            s = fmaf(self_vecs[n * DD + d], g_self_w[d], s);
        }
#pragma unroll
        for (int o = 16; o > 0; o >>= 1) s += __shfl_xor_sync(0xffffffffu, s, o);
        if (lane == 0) g_ts[n] = s;
    }
}

// ---------------------------------------------------------------------------
// Kernel A (persistent + pipelined): 296 CTAs, each owns nodes b, b+296, ...
//   Double-buffered neigh+link slots streamed via cp.async one iteration
//   ahead; B-fragments register-resident (loop-invariant); per-node compute
//   body is the proven R15 NPC=1 math.
// ---------------------------------------------------------------------------
__global__ __launch_bounds__(256, 2) void mma_agg_kernel(
    const float* __restrict__ neigh_vecs,
    const float* __restrict__ link_vecs,
    const float* __restrict__ select_probs,
    const float* __restrict__ g_neigh_w,
    const float* __restrict__ g_link_w)
{
    extern __shared__ char sm[];
    const uint sb  = smem_u32(sm);
    const int t    = threadIdx.x;
    const int wid  = t >> 5;
    const int lane = t & 31;
    const int g8   = lane >> 2;
    const int tig  = lane & 3;
    const int b    = blockIdx.x;
    const int iters = (NN - b + PCTA - 1) / PCTA;

    uint*   Asm      = (uint*)(sm + A_OFF);
    float*  dbuf     = (float*)(sm + DBUF_OFF);
    float*  tlink_s  = (float*)(sm + TLINK_OFF);
    float*  tneigh_s = (float*)(sm + TNEIGH_OFF);
    float*  wk_s     = (float*)(sm + WK_OFF);
    float*  gnw_s    = (float*)(sm + GNW_OFF);
    float*  glw_s    = (float*)(sm + GLW_OFF);

    // loop-invariant B fragments -> registers (this warp's 32 output cols)
    uint2 bfr[8][4];
#pragma unroll
    for (int kk = 0; kk < 8; kk++)
#pragma unroll
        for (int ni = 0; ni < 4; ni++)
            bfr[kk][ni] = g_Bfrag[((32 * wid + 8 * ni + g8) * 8 + kk) * 4 + tig];

    // small vectors (visible after first top-of-loop barrier)
    gnw_s[t] = g_neigh_w[t];
    if (t < LL) glw_s[t] = g_link_w[t];
    if (t < MM) wk_s[t] = 0.f;

    // prologue: prefetch node b into slot 0
    {
        const float4* ns = (const float4*)(neigh_vecs + (long)b * ROWS * DD);
        for (int idx = t; idx < NEIGH_SZ / 16; idx += 256)
            cp_async16(sb + SLOT_OFF + idx * 16, ns + idx);
        const float4* ls = (const float4*)(link_vecs + (long)b * ROWS * LL);
        for (int idx = t; idx < (SLOT_SZ - NEIGH_SZ) / 16; idx += 256)
            cp_async16(sb + SLOT_OFF + NEIGH_SZ + idx * 16, ls + idx);
    }
    CP_COMMIT();

    for (int i = 0; i < iters; i++) {
        const int n = b + i * PCTA;
        const int s = i & 1;
        const uint slot  = sb + SLOT_OFF + s * SLOT_SZ;
        float* neigh_s = (float*)(sm + SLOT_OFF + s * SLOT_SZ);
        float* link_s  = (float*)(sm + SLOT_OFF + s * SLOT_SZ + NEIGH_SZ);

        // prefetch next node into the other slot (safe: end-of-iter barrier
        // of iteration i-1 guarantees no thread still reads slot 1-s)
        if (i + 1 < iters) {
            const int n2 = n + PCTA;
            const uint o2 = sb + SLOT_OFF + (1 - s) * SLOT_SZ;
            const float4* ns = (const float4*)(neigh_vecs + (long)n2 * ROWS * DD);
            for (int idx = t; idx < NEIGH_SZ / 16; idx += 256)
                cp_async16(o2 + idx * 16, ns + idx);
            const float4* ls = (const float4*)(link_vecs + (long)n2 * ROWS * LL);
            for (int idx = t; idx < (SLOT_SZ - NEIGH_SZ) / 16; idx += 256)
                cp_async16(o2 + NEIGH_SZ + idx * 16, ls + idx);
        }
        CP_COMMIT();          // uniform group accounting (may be empty)
        CP_WAIT1();           // current slot's group (committed last iter) done
        __syncthreads();      // slot data + (iter 0) gnw/glw/wk visible

        // stage A as tf32 [32, AST] from link_s + tlink partial dots
        {
            int r = t >> 3, q = t & 7;
            bool valid = r < ROWS;
            const float4* src = (const float4*)(link_s + r * LL + 8 * q);
            const float4 z4 = make_float4(0.f, 0.f, 0.f, 0.f);
            float dl = 0.f;
#pragma unroll
            for (int u = 0; u < 2; u++) {
                float4 x = valid ? src[u] : z4;
                uint4 c4 = make_uint4(tf32r(x.x), tf32r(x.y), tf32r(x.z), tf32r(x.w));
                *(uint4*)&Asm[r * AST + 8 * q + 4 * u] = c4;
                int lb = 8 * q + 4 * u;
                dl = fmaf(x.x, glw_s[lb],     dl);
                dl = fmaf(x.y, glw_s[lb + 1], dl);
                dl = fmaf(x.z, glw_s[lb + 2], dl);
                dl = fmaf(x.w, glw_s[lb + 3], dl);
            }
            dl += __shfl_xor_sync(0xffffffffu, dl, 1);
            dl += __shfl_xor_sync(0xffffffffu, dl, 2);
            dl += __shfl_xor_sync(0xffffffffu, dl, 4);
            if (q == 0 && valid) tlink_s[r] = dl;
        }
        __syncthreads();      // Asm + tlink visible

        // MMA: S[32,256] = A[32,64] @ B; warp w owns cols [32w, 32w+32)
        float acc[2][4][4];
#pragma unroll
        for (int mi = 0; mi < 2; mi++)
#pragma unroll
            for (int ni = 0; ni < 4; ni++)
#pragma unroll
                for (int j = 0; j < 4; j++) acc[mi][ni][j] = 0.f;

#pragma unroll
        for (int kk = 0; kk < 8; kk++) {
            uint af[2][4];
#pragma unroll
            for (int mi = 0; mi < 2; mi++) {
                int e = (16 * mi + g8) * AST + 8 * kk + tig;
                af[mi][0] = Asm[e];
                af[mi][1] = Asm[e + 8 * AST];
                af[mi][2] = Asm[e + 4];
                af[mi][3] = Asm[e + 8 * AST + 4];
            }
#pragma unroll
            for (int ni = 0; ni < 4; ni++)
#pragma unroll
                for (int mi = 0; mi < 2; mi++)
                    mma_tf32(acc[mi][ni], af[mi], bfr[kk][ni].x, bfr[kk][ni].y);
        }

        // gate: trans_neigh warp-task dots, then wk
        for (int task = wid; task < ROWS; task += 8) {
            float sgd = 0.f;
#pragma unroll
            for (int q = 0; q < 8; q++) {
                int d = lane + 32 * q;
                sgd = fmaf(neigh_s[task * DD + d], gnw_s[d], sgd);
            }
#pragma unroll
            for (int o = 16; o > 0; o >>= 1) sgd += __shfl_xor_sync(0xffffffffu, sgd, o);
            if (lane == 0) tneigh_s[task] = sgd;
        }
        __syncthreads();
        if (t < ROWS) {
            float r  = g_ts[n] + tneigh_s[t] + tlink_s[t];
            float gt = 1.f / (1.f + __expf(-r));
            wk_s[t]  = gt / (select_probs[n * KN + t] * (float)KN);
        }
        __syncthreads();

        // epilogue A: sigmoid * wk -> dbuf[32][260]
#pragma unroll
        for (int mi = 0; mi < 2; mi++) {
            int row0 = 16 * mi + g8;
            float w0 = wk_s[row0], w1 = wk_s[row0 + 8];
#pragma unroll
            for (int ni = 0; ni < 4; ni++) {
                int col = 32 * wid + 8 * ni + 2 * tig;
                float2 v0, v1;
                v0.x = sigm_fast(acc[mi][ni][0]) * w0;
                v0.y = sigm_fast(acc[mi][ni][1]) * w0;
                v1.x = sigm_fast(acc[mi][ni][2]) * w1;
                v1.y = sigm_fast(acc[mi][ni][3]) * w1;
                *(float2*)&dbuf[row0 * 260 + col]       = v0;
                *(float2*)&dbuf[(row0 + 8) * 260 + col] = v1;
            }
        }
        __syncthreads();

        // epilogue B: reduce over k, write expected (col = t)
        {
            float a = 0.f;
#pragma unroll
            for (int j = 0; j < ROWS; j++)
                a = fmaf(dbuf[j * 260 + t], neigh_s[j * DD + t], a);
            g_expected[(long)n * DD + t] = a;
        }
        __syncthreads();      // end of iter: slot s + dbuf reads complete
    }
}

// ---------------------------------------------------------------------------
// Kernel B: out[:, coff:coff+256] = relu(A @ W)  (proven scalar FFMA2 pair)
// ---------------------------------------------------------------------------
__device__ __forceinline__ ull pk2(float lo, float hi) {
    ull r; asm("mov.b64 %0, {%1, %2};" : "=l"(r) : "f"(lo), "f"(hi)); return r;
}
__device__ __forceinline__ float2 upk2(ull v) {
    float2 f; asm("mov.b64 {%0, %1}, %2;" : "=f"(f.x), "=f"(f.y) : "l"(v)); return f;
}
__device__ __forceinline__ ull ffma2(ull a, ull b, ull c) {
    ull d; asm("fma.rn.f32x2 %0, %1, %2, %3;" : "=l"(d) : "l"(a), "l"(b), "l"(c)); return d;
}

__global__ __launch_bounds__(256) void gemm_relu_kernel(
    const float* __restrict__ A_in,
    const float* __restrict__ W,
    float* __restrict__ out,
    int coff, int use_expected)
{
    const float* __restrict__ A = use_expected ? (const float*)g_expected : A_in;

    __shared__ float As[64][32];
    __shared__ alignas(16) float Ws[32][64];

    const int tid = threadIdx.x;
    const int tx  = tid & 15;
    const int ty  = tid >> 4;
    const int r0  = blockIdx.x * 64;
    const int c0  = blockIdx.y * 64;

    ull acc[4][2];
#pragma unroll
    for (int i = 0; i < 4; i++) { acc[i][0] = 0ull; acc[i][1] = 0ull; }

    for (int kb = 0; kb < DD; kb += 32) {
#pragma unroll
        for (int u = 0; u < 2; u++) {
            int idx = tid + u * 256;
            int m = idx >> 3, q = idx & 7;
            *(float4*)&As[m][q * 4] =
                *(const float4*)&A[(size_t)(r0 + m) * DD + kb + q * 4];
        }
#pragma unroll
        for (int u = 0; u < 2; u++) {
            int idx = tid + u * 256;
            int kk = idx >> 4, q = idx & 15;
            *(float4*)&Ws[kk][q * 4] =
                *(const float4*)&W[(size_t)(kb + kk) * DD + c0 + q * 4];
        }
        __syncthreads();
#pragma unroll
        for (int kk = 0; kk < 32; kk++) {
            ulonglong2 b2 = *(const ulonglong2*)&Ws[kk][tx * 4];
#pragma unroll
            for (int i = 0; i < 4; i++) {
                float a = As[ty * 4 + i][kk];
                ull aa = pk2(a, a);
                acc[i][0] = ffma2(aa, b2.x, acc[i][0]);
                acc[i][1] = ffma2(aa, b2.y, acc[i][1]);
            }
        }
        __syncthreads();
    }

#pragma unroll
    for (int i = 0; i < 4; i++) {
        float2 r01 = upk2(acc[i][0]);
        float2 r23 = upk2(acc[i][1]);
        float4 o;
        o.x = fmaxf(r01.x, 0.f);
        o.y = fmaxf(r01.y, 0.f);
        o.z = fmaxf(r23.x, 0.f);
        o.w = fmaxf(r23.y, 0.f);
        *(float4*)&out[(size_t)(r0 + ty * 4 + i) * 512 + coff + c0 + tx * 4] = o;
    }
}

extern "C" void kernel_launch(void* const* d_in, const int* in_sizes, int n_in,
                              void* d_out, int out_size)
{
    const float* self_vecs    = (const float*)d_in[0];
    const float* neigh_vecs   = (const float*)d_in[1];
    const float* link_vecs    = (const float*)d_in[2];
    const float* select_probs = (const float*)d_in[3];
    const float* g_self_w     = (const float*)d_in[4];
    const float* g_neigh_w    = (const float*)d_in[5];
    const float* g_link_w     = (const float*)d_in[6];
    const float* W_link       = (const float*)d_in[7];
    const float* W_self       = (const float*)d_in[8];
    const float* W_neigh      = (const float*)d_in[9];
    float* out = (float*)d_out;

    static int attr_set = 0;
    if (!attr_set) {
        cudaFuncSetAttribute(mma_agg_kernel,
                             cudaFuncAttributeMaxDynamicSharedMemorySize, SMEM_TOTAL);
        attr_set = 1;
    }

    conv_w_kernel<<<32, 256>>>(W_link);
    ts_kernel<<<64, 256>>>(self_vecs, g_self_w);

    mma_agg_kernel<<<PCTA, 256, SMEM_TOTAL>>>(neigh_vecs, link_vecs, select_probs,
                                              g_neigh_w, g_link_w);

    dim3 g(NN / 64, 256 / 64);
    gemm_relu_kernel<<<g, 256>>>(self_vecs, W_self, out, 0, 0);
    gemm_relu_kernel<<<g, 256>>>(nullptr, W_neigh, out, 256, 1);
}